// round 13
// baseline (speedup 1.0000x reference)
#include <cuda_runtime.h>
#include <math.h>

typedef unsigned long long u64;

__device__ __forceinline__ u64 dup2(float v){
    u64 r; asm("mov.b64 %0, {%1, %1};" : "=l"(r) : "f"(v)); return r;
}
__device__ __forceinline__ u64 pk2(float lo, float hi){
    u64 r; asm("mov.b64 %0, {%1, %2};" : "=l"(r) : "f"(lo), "f"(hi)); return r;
}
__device__ __forceinline__ void upk2(u64 a, float &lo, float &hi){
    asm("mov.b64 {%0, %1}, %2;" : "=f"(lo), "=f"(hi) : "l"(a));
}
__device__ __forceinline__ u64 fma2(u64 a, u64 b, u64 c){
    u64 d; asm("fma.rn.f32x2 %0, %1, %2, %3;" : "=l"(d) : "l"(a), "l"(b), "l"(c)); return d;
}
__device__ __forceinline__ u64 add2(u64 a, u64 b){
    u64 c; asm("add.rn.f32x2 %0, %1, %2;" : "=l"(c) : "l"(a), "l"(b)); return c;
}
__device__ __forceinline__ u64 lds2(const float* p){ return *reinterpret_cast<const u64*>(p); }
__device__ __forceinline__ u64 bfly64(u64 v, int m){
    unsigned lo = (unsigned)v, hi = (unsigned)(v >> 32);
    lo = __shfl_xor_sync(0xffffffffu, lo, m);
    hi = __shfl_xor_sync(0xffffffffu, hi, m);
    return ((u64)hi << 32) | (u64)lo;
}

// ---------- one fused constant bank: W (u64 0..505) then b (u64 506..549) ----------
__constant__ u64 c_WB2[550];
#define CB_B 506

// ---------- device globals ----------
__device__ float g_wc[1586];     // Wc padded: node stride 66, bc at [1584..1585]
__device__ float g_pack[1100];   // staging for c_WB2
__device__ u64   g_csr[384];     // 24 nodes x 16 entries: (f32 a)<<32 | src_node
__device__ int   g_maxn;

// ---------- merged prologue ----------
__global__ void prologue_kernel(const int* __restrict__ ei_raw,
                                const float* __restrict__ W1, const float* __restrict__ b1,
                                const float* __restrict__ W2, const float* __restrict__ b2,
                                const float* __restrict__ W3, const float* __restrict__ b3,
                                const float* __restrict__ W4, const float* __restrict__ b4,
                                const float* __restrict__ W5, const float* __restrict__ b5,
                                const float* __restrict__ W6, const float* __restrict__ b6,
                                const float* __restrict__ W7, const float* __restrict__ b7,
                                const float* __restrict__ fcw1, const float* __restrict__ fcb1,
                                const float* __restrict__ fcw2, const float* __restrict__ fcb2){
    __shared__ float sdeg[24], sdinv[24], sAl[576];
    __shared__ float sw2[256];
    __shared__ int ssrc[96], sdst[96];
    __shared__ int is64, scnt[24], smax;
    int t = threadIdx.x;      // 768 threads

    if (t < 4)    g_pack[0    + t] = W1[t];
    if (t < 16)   g_pack[4    + t] = W2[t];
    if (t < 32)   g_pack[20   + t] = W3[t];
    if (t < 64)   g_pack[52   + t] = W4[t];
    if (t < 128)  g_pack[116  + t] = W5[t];
    if (t < 256)  g_pack[244  + t] = W6[t];
    if (t < 512)  g_pack[500  + t] = W7[t];
    if (t < 4)    g_pack[1012 + t] = b1[t];
    if (t < 4)    g_pack[1016 + t] = b2[t];
    if (t < 8)    g_pack[1020 + t] = b3[t];
    if (t < 8)    g_pack[1028 + t] = b4[t];
    if (t < 16)   g_pack[1036 + t] = b5[t];
    if (t < 16)   g_pack[1052 + t] = b6[t];
    if (t < 32)   g_pack[1068 + t] = b7[t];

    if (t == 0){
        int z = 1;
        #pragma unroll 1
        for (int i = 1; i < 192; i += 2) if (ei_raw[i] != 0){ z = 0; break; }
        is64 = z;
        smax = 0;
    }
    if (t < 24) sdeg[t] = 1.0f;
    if (t < 576) sAl[t] = 0.0f;
    if (t >= 576 && t < 768) sw2[(t - 576)] = fcw2[t - 576];
    if (t < 64) sw2[192 + t] = fcw2[192 + t];
    __syncthreads();
    if (t < 96){
        int s, d;
        if (is64){
            const long long* e = reinterpret_cast<const long long*>(ei_raw);
            s = (int)e[t]; d = (int)e[96 + t];
        } else { s = ei_raw[t]; d = ei_raw[96 + t]; }
        s = min(max(s,0),23); d = min(max(d,0),23);
        ssrc[t] = s; sdst[t] = d;
        atomicAdd(&sdeg[d], 1.0f);
    }
    __syncthreads();
    if (t < 24) sdinv[t] = 1.0f / sqrtf(sdeg[t]);
    __syncthreads();
    if (t < 96) atomicAdd(&sAl[sdst[t]*24 + ssrc[t]], sdinv[ssrc[t]]*sdinv[sdst[t]]);
    if (t < 24) atomicAdd(&sAl[t*24 + t], sdinv[t]*sdinv[t]);
    __syncthreads();

    // ---- CSR: (a, src) pairs, 16-entry cap per node ----
    if (t < 24){
        int c = 0;
        #pragma unroll 1
        for (int j = 0; j < 24; j++){
            float a = sAl[t*24 + j];
            if (a != 0.0f && c < 16){
                g_csr[t*16 + c] = ((u64)__float_as_uint(a) << 32) | (u64)(unsigned)j;
                c++;
            }
        }
        scnt[t] = c;
        atomicMax(&smax, c);
    }
    __syncthreads();
    if (t < 24){
        for (int k = scnt[t]; k < 16; k++) g_csr[t*16 + k] = 0ull;  // a=0, src=0
    }
    if (t == 0) g_maxn = min(smax, 16);

    // ---- Wc = fcw1 @ fcw2 (padded), bc = fcb1 @ fcw2 + fcb2 ----
    {
        float a0 = 0.f, a1 = 0.f;
        const float* row = fcw1 + t * 128;
        #pragma unroll 8
        for (int k = 0; k < 128; k++){
            float w = row[k];
            a0 += w * sw2[2*k];
            a1 += w * sw2[2*k + 1];
        }
        int node = t >> 5, fi = t & 31;
        g_wc[node*66 + 2*fi]     = a0;
        g_wc[node*66 + 2*fi + 1] = a1;
        if (t < 2){
            float b = fcb2[t];
            #pragma unroll 8
            for (int k = 0; k < 128; k++) b += fcb1[k] * sw2[2*k + t];
            g_wc[1584 + t] = b;
        }
    }
}

// ---------- fused GCN kernel: warp = batch, lane = node, H in registers ----------
#define NT 256
#define TB 8

template<int FIN, int FOUT, int W2, int B2>
__device__ __forceinline__ void gcn_layer(float* h, const u64* csr, int maxn)
{
    float g[FIN];
    #pragma unroll
    for (int f = 0; f < FIN; f++) g[f] = 0.f;
    #pragma unroll 4
    for (int k = 0; k < maxn; k++){          // maxn block-uniform -> converged shfl
        u64 e = csr[k];
        int src = (int)(unsigned)e;
        float ak = __uint_as_float((unsigned)(e >> 32));
        #pragma unroll
        for (int f = 0; f < FIN; f++)
            g[f] = fmaf(ak, __shfl_sync(0xffffffffu, h[f], src), g[f]);
    }
    constexpr int KP = FOUT/2;
    u64 acc[KP];
    #pragma unroll
    for (int k = 0; k < KP; k++) acc[k] = c_WB2[CB_B + B2 + k];
    #pragma unroll
    for (int fi = 0; fi < FIN; fi++){
        u64 d = dup2(g[fi]);
        #pragma unroll
        for (int k = 0; k < KP; k++)
            acc[k] = fma2(d, c_WB2[W2 + fi*KP + k], acc[k]);
    }
    #pragma unroll
    for (int k = 0; k < KP; k++){
        float lo, hi; upk2(acc[k], lo, hi);
        h[2*k]   = fmaxf(lo, 0.f);
        h[2*k+1] = fmaxf(hi, 0.f);
    }
}

__global__ __launch_bounds__(NT, 3)
void gcn_fused_kernel(const float* __restrict__ x, float* __restrict__ out)
{
    __shared__ float sWc[1586];
    __shared__ u64   sCsr[24*17];     // stride 17: conflict-spread
    __shared__ int   sMx;

    const int t = threadIdx.x;
    const int warp = t >> 5;
    const int lane = t & 31;

    for (int i = t; i < 1586; i += NT) sWc[i] = g_wc[i];
    for (int i = t; i < 384;  i += NT) sCsr[(i >> 4)*17 + (i & 15)] = g_csr[i];
    if (t == 0) sMx = g_maxn;

    const int node = (lane < 24) ? lane : 0;
    const u64* csr = sCsr + node * 17;
    const int gb = blockIdx.x * TB + warp;

    float h[16];
    h[0] = (lane < 24) ? x[gb*24 + lane] : 0.f;
    __syncthreads();
    const int maxn = sMx;

    gcn_layer< 1,  4,   0,  0>(h, csr, maxn);
    gcn_layer< 4,  4,   2,  2>(h, csr, maxn);
    gcn_layer< 4,  8,  10,  4>(h, csr, maxn);
    gcn_layer< 8,  8,  26,  8>(h, csr, maxn);
    gcn_layer< 8, 16,  58, 12>(h, csr, maxn);
    gcn_layer<16, 16, 122, 20>(h, csr, maxn);

    // ---- layer 7 (16->32) + folded FC head, all in registers ----
    float g[16];
    #pragma unroll
    for (int f = 0; f < 16; f++) g[f] = 0.f;
    #pragma unroll 4
    for (int k = 0; k < maxn; k++){
        u64 e = csr[k];
        int src = (int)(unsigned)e;
        float ak = __uint_as_float((unsigned)(e >> 32));
        #pragma unroll
        for (int f = 0; f < 16; f++)
            g[f] = fmaf(ak, __shfl_sync(0xffffffffu, h[f], src), g[f]);
    }
    u64 z = 0ull;
    const float* wcn = sWc + node * 66;
    #pragma unroll
    for (int pass = 0; pass < 2; pass++){
        u64 acc[8];
        #pragma unroll
        for (int k = 0; k < 8; k++) acc[k] = c_WB2[CB_B + 28 + pass*8 + k];
        #pragma unroll
        for (int fi = 0; fi < 16; fi++){
            u64 d = dup2(g[fi]);
            #pragma unroll
            for (int k = 0; k < 8; k++)
                acc[k] = fma2(d, c_WB2[250 + fi*16 + pass*8 + k], acc[k]);
        }
        const float* wcp = wcn + pass * 32;
        #pragma unroll
        for (int k = 0; k < 8; k++){
            float a, b; upk2(acc[k], a, b);
            z = fma2(dup2(fmaxf(a, 0.f)), lds2(wcp + 4*k),     z);
            z = fma2(dup2(fmaxf(b, 0.f)), lds2(wcp + 4*k + 2), z);
        }
    }
    if (lane >= 24) z = 0ull;

    #pragma unroll
    for (int m = 16; m >= 1; m >>= 1) z = add2(z, bfly64(z, m));
    if (lane == 0){
        z = add2(z, lds2(sWc + 1584));     // bc
        float z0, z1; upk2(z, z0, z1);
        float mx = fmaxf(z0, z1);
        float lse = mx + logf(expf(z0 - mx) + expf(z1 - mx));
        reinterpret_cast<u64*>(out)[gb] = pk2(z0 - lse, z1 - lse);
    }
}

extern "C" void kernel_launch(void* const* d_in, const int* in_sizes, int n_in,
                              void* d_out, int out_size)
{
    const float* x  = (const float*)d_in[0];
    const int*   ei = (const int*)d_in[1];
    float* out = (float*)d_out;

    const int B = in_sizes[0] / 24;
    const int grid = B / TB;           // 4096

    prologue_kernel<<<1, 768>>>(ei,
        (const float*)d_in[2],  (const float*)d_in[3],
        (const float*)d_in[4],  (const float*)d_in[5],
        (const float*)d_in[6],  (const float*)d_in[7],
        (const float*)d_in[8],  (const float*)d_in[9],
        (const float*)d_in[10], (const float*)d_in[11],
        (const float*)d_in[12], (const float*)d_in[13],
        (const float*)d_in[14], (const float*)d_in[15],
        (const float*)d_in[16], (const float*)d_in[17],
        (const float*)d_in[18], (const float*)d_in[19]);

    // plain DtoD memcpy into the constant bank's device address —
    // avoids the memcpy-to-symbol graph node (const-bank patch path, ~54us/replay)
    void* packAddr = nullptr;
    void* cAddr = nullptr;
    cudaGetSymbolAddress(&packAddr, g_pack);
    cudaGetSymbolAddress(&cAddr, c_WB2);
    cudaMemcpyAsync(cAddr, packAddr, 1100*4, cudaMemcpyDeviceToDevice, 0);

    gcn_fused_kernel<<<grid, NT>>>(x, out);
}

// round 14
// speedup vs baseline: 1.4787x; 1.4787x over previous
#include <cuda_runtime.h>
#include <math.h>

typedef unsigned long long u64;

__device__ __forceinline__ u64 dup2(float v){
    u64 r; asm("mov.b64 %0, {%1, %1};" : "=l"(r) : "f"(v)); return r;
}
__device__ __forceinline__ u64 pk2(float lo, float hi){
    u64 r; asm("mov.b64 %0, {%1, %2};" : "=l"(r) : "f"(lo), "f"(hi)); return r;
}
__device__ __forceinline__ void upk2(u64 a, float &lo, float &hi){
    asm("mov.b64 {%0, %1}, %2;" : "=f"(lo), "=f"(hi) : "l"(a));
}
__device__ __forceinline__ u64 fma2(u64 a, u64 b, u64 c){
    u64 d; asm("fma.rn.f32x2 %0, %1, %2, %3;" : "=l"(d) : "l"(a), "l"(b), "l"(c)); return d;
}
__device__ __forceinline__ u64 add2(u64 a, u64 b){
    u64 c; asm("add.rn.f32x2 %0, %1, %2;" : "=l"(c) : "l"(a), "l"(b)); return c;
}
__device__ __forceinline__ u64 lds2(const float* p){ return *reinterpret_cast<const u64*>(p); }
__device__ __forceinline__ u64 bfly64(u64 v, int m){
    unsigned lo = (unsigned)v, hi = (unsigned)(v >> 32);
    lo = __shfl_xor_sync(0xffffffffu, lo, m);
    hi = __shfl_xor_sync(0xffffffffu, hi, m);
    return ((u64)hi << 32) | (u64)lo;
}

// ---------- one fused constant bank: W (u64 0..505) then b (u64 506..549) ----------
__constant__ u64 c_WB2[550];
#define CB_B 506

// ---------- device globals ----------
__device__ float g_wc[1586];     // Wc padded: node stride 66, bc at [1584..1585]
__device__ float g_pack[1100];   // staging for c_WB2
__device__ u64   g_csr[384];     // 24 nodes x 16 entries: (f32 a)<<32 | src_node
__device__ int   g_maxn;

// ---------- parallel prologue: 7 blocks x 768 threads ----------
// block 0: adjacency + CSR + weight packing
// blocks 1..6: Wc rows (b-1)*128 .. +128 (smem-staged fcw1 chunk, coalesced)
constexpr int PRO_SMEM_FLOATS = 256 + 128*129 + 128;   // sw2 + chunk + fcb1
constexpr int PRO_SMEM_BYTES  = PRO_SMEM_FLOATS * 4;   // 67584+... = 68112B

__global__ void prologue_kernel(const int* __restrict__ ei_raw,
                                const float* __restrict__ W1, const float* __restrict__ b1,
                                const float* __restrict__ W2, const float* __restrict__ b2,
                                const float* __restrict__ W3, const float* __restrict__ b3,
                                const float* __restrict__ W4, const float* __restrict__ b4,
                                const float* __restrict__ W5, const float* __restrict__ b5,
                                const float* __restrict__ W6, const float* __restrict__ b6,
                                const float* __restrict__ W7, const float* __restrict__ b7,
                                const float* __restrict__ fcw1, const float* __restrict__ fcb1,
                                const float* __restrict__ fcw2, const float* __restrict__ fcb2){
    extern __shared__ float dyn[];           // [0..255]=sw2, [256..]=chunk(stride129), tail=fcb1
    int t = threadIdx.x;                     // 768 threads
    int blk = blockIdx.x;

    if (blk == 0){
        // ---- weight/bias packing ----
        if (t < 4)    g_pack[0    + t] = W1[t];
        if (t < 16)   g_pack[4    + t] = W2[t];
        if (t < 32)   g_pack[20   + t] = W3[t];
        if (t < 64)   g_pack[52   + t] = W4[t];
        if (t < 128)  g_pack[116  + t] = W5[t];
        if (t < 256)  g_pack[244  + t] = W6[t];
        if (t < 512)  g_pack[500  + t] = W7[t];
        if (t < 4)    g_pack[1012 + t] = b1[t];
        if (t < 4)    g_pack[1016 + t] = b2[t];
        if (t < 8)    g_pack[1020 + t] = b3[t];
        if (t < 8)    g_pack[1028 + t] = b4[t];
        if (t < 16)   g_pack[1036 + t] = b5[t];
        if (t < 16)   g_pack[1052 + t] = b6[t];
        if (t < 32)   g_pack[1068 + t] = b7[t];

        __shared__ float sdeg[24], sdinv[24], sAl[576];
        __shared__ int ssrc[96], sdst[96];
        __shared__ int scnt[24], smax;

        // is64 vote: int64 edge_index has all odd 32-bit words zero
        int myok = (t < 96) ? (ei_raw[2*t + 1] == 0) : 1;
        int is64 = __syncthreads_and(myok);

        if (t == 0) smax = 0;
        if (t < 24) sdeg[t] = 1.0f;
        if (t < 576) sAl[t] = 0.0f;
        __syncthreads();
        if (t < 96){
            int s, d;
            if (is64){
                const long long* e = reinterpret_cast<const long long*>(ei_raw);
                s = (int)e[t]; d = (int)e[96 + t];
            } else { s = ei_raw[t]; d = ei_raw[96 + t]; }
            s = min(max(s,0),23); d = min(max(d,0),23);
            ssrc[t] = s; sdst[t] = d;
            atomicAdd(&sdeg[d], 1.0f);
        }
        __syncthreads();
        if (t < 24) sdinv[t] = 1.0f / sqrtf(sdeg[t]);
        __syncthreads();
        if (t < 96) atomicAdd(&sAl[sdst[t]*24 + ssrc[t]], sdinv[ssrc[t]]*sdinv[sdst[t]]);
        if (t < 24) atomicAdd(&sAl[t*24 + t], sdinv[t]*sdinv[t]);
        __syncthreads();

        // CSR: (a, src) pairs, 16-entry cap
        if (t < 24){
            int c = 0;
            #pragma unroll 1
            for (int j = 0; j < 24; j++){
                float a = sAl[t*24 + j];
                if (a != 0.0f && c < 16){
                    g_csr[t*16 + c] = ((u64)__float_as_uint(a) << 32) | (u64)(unsigned)j;
                    c++;
                }
            }
            scnt[t] = c;
            atomicMax(&smax, c);
        }
        __syncthreads();
        if (t < 24){
            for (int k = scnt[t]; k < 16; k++) g_csr[t*16 + k] = 0ull;
        }
        if (t == 0) g_maxn = min(smax, 16);
    } else {
        // ---- Wc rows [r0, r0+128) ----
        const int r0 = (blk - 1) * 128;
        float* sw2   = dyn;
        float* chunk = dyn + 256;          // row stride 129 (conflict-free)
        float* sb1   = dyn + 256 + 128*129;

        if (t < 256) sw2[t] = fcw2[t];
        if (t < 128) sb1[t] = fcb1[t];
        const float* src = fcw1 + r0 * 128;
        for (int i = t; i < 16384; i += 768){
            int row = i >> 7, col = i & 127;
            chunk[row*129 + col] = src[i];   // coalesced gmem reads
        }
        __syncthreads();

        if (t < 128){
            const float* row = chunk + t * 129;
            float a0 = 0.f, a1 = 0.f;
            #pragma unroll 8
            for (int k = 0; k < 128; k++){
                float w = row[k];
                a0 += w * sw2[2*k];
                a1 += w * sw2[2*k + 1];
            }
            int f = r0 + t;
            int node = f >> 5, fi = f & 31;
            g_wc[node*66 + 2*fi]     = a0;
            g_wc[node*66 + 2*fi + 1] = a1;
        }
        if (blk == 1 && t < 2){
            float b = fcb2[t];
            #pragma unroll 8
            for (int k = 0; k < 128; k++) b += sb1[k] * sw2[2*k + t];
            g_wc[1584 + t] = b;
        }
    }
}

// ---------- fused GCN kernel: warp = batch, lane = node, H in registers ----------
#define NT 256
#define TB 8

template<int FIN, int FOUT, int W2, int B2>
__device__ __forceinline__ void gcn_layer(float* h, const u64* csr, int maxn)
{
    float g[FIN];
    #pragma unroll
    for (int f = 0; f < FIN; f++) g[f] = 0.f;
    #pragma unroll 4
    for (int k = 0; k < maxn; k++){          // maxn block-uniform -> converged shfl
        u64 e = csr[k];
        int src = (int)(unsigned)e;
        float ak = __uint_as_float((unsigned)(e >> 32));
        #pragma unroll
        for (int f = 0; f < FIN; f++)
            g[f] = fmaf(ak, __shfl_sync(0xffffffffu, h[f], src), g[f]);
    }
    constexpr int KP = FOUT/2;
    u64 acc[KP];
    #pragma unroll
    for (int k = 0; k < KP; k++) acc[k] = c_WB2[CB_B + B2 + k];
    #pragma unroll
    for (int fi = 0; fi < FIN; fi++){
        u64 d = dup2(g[fi]);
        #pragma unroll
        for (int k = 0; k < KP; k++)
            acc[k] = fma2(d, c_WB2[W2 + fi*KP + k], acc[k]);
    }
    #pragma unroll
    for (int k = 0; k < KP; k++){
        float lo, hi; upk2(acc[k], lo, hi);
        h[2*k]   = fmaxf(lo, 0.f);
        h[2*k+1] = fmaxf(hi, 0.f);
    }
}

__global__ __launch_bounds__(NT, 3)
void gcn_fused_kernel(const float* __restrict__ x, float* __restrict__ out)
{
    __shared__ float sWc[1586];
    __shared__ u64   sCsr[24*17];     // stride 17: conflict-spread
    __shared__ int   sMx;

    const int t = threadIdx.x;
    const int warp = t >> 5;
    const int lane = t & 31;

    for (int i = t; i < 1586; i += NT) sWc[i] = g_wc[i];
    for (int i = t; i < 384;  i += NT) sCsr[(i >> 4)*17 + (i & 15)] = g_csr[i];
    if (t == 0) sMx = g_maxn;

    const int node = (lane < 24) ? lane : 0;
    const u64* csr = sCsr + node * 17;
    const int gb = blockIdx.x * TB + warp;

    float h[16];
    h[0] = (lane < 24) ? x[gb*24 + lane] : 0.f;
    __syncthreads();
    const int maxn = sMx;

    gcn_layer< 1,  4,   0,  0>(h, csr, maxn);
    gcn_layer< 4,  4,   2,  2>(h, csr, maxn);
    gcn_layer< 4,  8,  10,  4>(h, csr, maxn);
    gcn_layer< 8,  8,  26,  8>(h, csr, maxn);
    gcn_layer< 8, 16,  58, 12>(h, csr, maxn);
    gcn_layer<16, 16, 122, 20>(h, csr, maxn);

    // ---- layer 7 (16->32) + folded FC head, all in registers ----
    float g[16];
    #pragma unroll
    for (int f = 0; f < 16; f++) g[f] = 0.f;
    #pragma unroll 4
    for (int k = 0; k < maxn; k++){
        u64 e = csr[k];
        int src = (int)(unsigned)e;
        float ak = __uint_as_float((unsigned)(e >> 32));
        #pragma unroll
        for (int f = 0; f < 16; f++)
            g[f] = fmaf(ak, __shfl_sync(0xffffffffu, h[f], src), g[f]);
    }
    u64 z = 0ull;
    const float* wcn = sWc + node * 66;
    #pragma unroll
    for (int pass = 0; pass < 2; pass++){
        u64 acc[8];
        #pragma unroll
        for (int k = 0; k < 8; k++) acc[k] = c_WB2[CB_B + 28 + pass*8 + k];
        #pragma unroll
        for (int fi = 0; fi < 16; fi++){
            u64 d = dup2(g[fi]);
            #pragma unroll
            for (int k = 0; k < 8; k++)
                acc[k] = fma2(d, c_WB2[250 + fi*16 + pass*8 + k], acc[k]);
        }
        const float* wcp = wcn + pass * 32;
        #pragma unroll
        for (int k = 0; k < 8; k++){
            float a, b; upk2(acc[k], a, b);
            z = fma2(dup2(fmaxf(a, 0.f)), lds2(wcp + 4*k),     z);
            z = fma2(dup2(fmaxf(b, 0.f)), lds2(wcp + 4*k + 2), z);
        }
    }
    if (lane >= 24) z = 0ull;

    #pragma unroll
    for (int m = 16; m >= 1; m >>= 1) z = add2(z, bfly64(z, m));
    if (lane == 0){
        z = add2(z, lds2(sWc + 1584));     // bc
        float z0, z1; upk2(z, z0, z1);
        float mx = fmaxf(z0, z1);
        float lse = mx + logf(expf(z0 - mx) + expf(z1 - mx));
        reinterpret_cast<u64*>(out)[gb] = pk2(z0 - lse, z1 - lse);
    }
}

extern "C" void kernel_launch(void* const* d_in, const int* in_sizes, int n_in,
                              void* d_out, int out_size)
{
    const float* x  = (const float*)d_in[0];
    const int*   ei = (const int*)d_in[1];
    float* out = (float*)d_out;

    const int B = in_sizes[0] / 24;
    const int grid = B / TB;           // 4096

    cudaFuncSetAttribute(prologue_kernel,
                         cudaFuncAttributeMaxDynamicSharedMemorySize, PRO_SMEM_BYTES);

    prologue_kernel<<<7, 768, PRO_SMEM_BYTES>>>(ei,
        (const float*)d_in[2],  (const float*)d_in[3],
        (const float*)d_in[4],  (const float*)d_in[5],
        (const float*)d_in[6],  (const float*)d_in[7],
        (const float*)d_in[8],  (const float*)d_in[9],
        (const float*)d_in[10], (const float*)d_in[11],
        (const float*)d_in[12], (const float*)d_in[13],
        (const float*)d_in[14], (const float*)d_in[15],
        (const float*)d_in[16], (const float*)d_in[17],
        (const float*)d_in[18], (const float*)d_in[19]);

    void* packAddr = nullptr;
    void* cAddr = nullptr;
    cudaGetSymbolAddress(&packAddr, g_pack);
    cudaGetSymbolAddress(&cAddr, c_WB2);
    cudaMemcpyAsync(cAddr, packAddr, 1100*4, cudaMemcpyDeviceToDevice, 0);

    gcn_fused_kernel<<<grid, NT>>>(x, out);
}

// round 15
// speedup vs baseline: 1.5413x; 1.0423x over previous
#include <cuda_runtime.h>
#include <math.h>

typedef unsigned long long u64;

__device__ __forceinline__ u64 dup2(float v){
    u64 r; asm("mov.b64 %0, {%1, %1};" : "=l"(r) : "f"(v)); return r;
}
__device__ __forceinline__ u64 pk2(float lo, float hi){
    u64 r; asm("mov.b64 %0, {%1, %2};" : "=l"(r) : "f"(lo), "f"(hi)); return r;
}
__device__ __forceinline__ void upk2(u64 a, float &lo, float &hi){
    asm("mov.b64 {%0, %1}, %2;" : "=f"(lo), "=f"(hi) : "l"(a));
}
__device__ __forceinline__ u64 fma2(u64 a, u64 b, u64 c){
    u64 d; asm("fma.rn.f32x2 %0, %1, %2, %3;" : "=l"(d) : "l"(a), "l"(b), "l"(c)); return d;
}
__device__ __forceinline__ u64 add2(u64 a, u64 b){
    u64 c; asm("add.rn.f32x2 %0, %1, %2;" : "=l"(c) : "l"(a), "l"(b)); return c;
}
__device__ __forceinline__ u64 lds2(const float* p){ return *reinterpret_cast<const u64*>(p); }
__device__ __forceinline__ u64 bfly64(u64 v, int m){
    unsigned lo = (unsigned)v, hi = (unsigned)(v >> 32);
    lo = __shfl_xor_sync(0xffffffffu, lo, m);
    hi = __shfl_xor_sync(0xffffffffu, hi, m);
    return ((u64)hi << 32) | (u64)lo;
}

// ---------- one fused constant bank: W (u64 0..505) then b (u64 506..549) ----------
__constant__ u64 c_WB2[550];
#define CB_B 506

// ---------- device globals ----------
__device__ float g_wc[1586];     // Wc padded: node stride 66, bc at [1584..1585]
__device__ float g_pack[1100];   // staging for c_WB2
__device__ u64   g_csr[384];     // 24 nodes x 16 entries: (f32 a)<<32 | src_node
__device__ int   g_maxn;

// ---------- parallel prologue: 7 blocks x 768 threads ----------
constexpr int PRO_SMEM_FLOATS = 256 + 128*129 + 128;
constexpr int PRO_SMEM_BYTES  = PRO_SMEM_FLOATS * 4;

__global__ void prologue_kernel(const int* __restrict__ ei_raw,
                                const float* __restrict__ W1, const float* __restrict__ b1,
                                const float* __restrict__ W2, const float* __restrict__ b2,
                                const float* __restrict__ W3, const float* __restrict__ b3,
                                const float* __restrict__ W4, const float* __restrict__ b4,
                                const float* __restrict__ W5, const float* __restrict__ b5,
                                const float* __restrict__ W6, const float* __restrict__ b6,
                                const float* __restrict__ W7, const float* __restrict__ b7,
                                const float* __restrict__ fcw1, const float* __restrict__ fcb1,
                                const float* __restrict__ fcw2, const float* __restrict__ fcb2){
    extern __shared__ float dyn[];
    int t = threadIdx.x;                     // 768 threads
    int blk = blockIdx.x;

    if (blk == 0){
        if (t < 4)    g_pack[0    + t] = W1[t];
        if (t < 16)   g_pack[4    + t] = W2[t];
        if (t < 32)   g_pack[20   + t] = W3[t];
        if (t < 64)   g_pack[52   + t] = W4[t];
        if (t < 128)  g_pack[116  + t] = W5[t];
        if (t < 256)  g_pack[244  + t] = W6[t];
        if (t < 512)  g_pack[500  + t] = W7[t];
        if (t < 4)    g_pack[1012 + t] = b1[t];
        if (t < 4)    g_pack[1016 + t] = b2[t];
        if (t < 8)    g_pack[1020 + t] = b3[t];
        if (t < 8)    g_pack[1028 + t] = b4[t];
        if (t < 16)   g_pack[1036 + t] = b5[t];
        if (t < 16)   g_pack[1052 + t] = b6[t];
        if (t < 32)   g_pack[1068 + t] = b7[t];

        __shared__ float sdeg[24], sdinv[24], sAl[576];
        __shared__ int ssrc[96], sdst[96];
        __shared__ int scnt[24], smax;

        int myok = (t < 96) ? (ei_raw[2*t + 1] == 0) : 1;
        int is64 = __syncthreads_and(myok);

        if (t == 0) smax = 0;
        if (t < 24) sdeg[t] = 1.0f;
        if (t < 576) sAl[t] = 0.0f;
        __syncthreads();
        if (t < 96){
            int s, d;
            if (is64){
                const long long* e = reinterpret_cast<const long long*>(ei_raw);
                s = (int)e[t]; d = (int)e[96 + t];
            } else { s = ei_raw[t]; d = ei_raw[96 + t]; }
            s = min(max(s,0),23); d = min(max(d,0),23);
            ssrc[t] = s; sdst[t] = d;
            atomicAdd(&sdeg[d], 1.0f);
        }
        __syncthreads();
        if (t < 24) sdinv[t] = 1.0f / sqrtf(sdeg[t]);
        __syncthreads();
        if (t < 96) atomicAdd(&sAl[sdst[t]*24 + ssrc[t]], sdinv[ssrc[t]]*sdinv[sdst[t]]);
        if (t < 24) atomicAdd(&sAl[t*24 + t], sdinv[t]*sdinv[t]);
        __syncthreads();

        if (t < 24){
            int c = 0;
            #pragma unroll 1
            for (int j = 0; j < 24; j++){
                float a = sAl[t*24 + j];
                if (a != 0.0f && c < 16){
                    g_csr[t*16 + c] = ((u64)__float_as_uint(a) << 32) | (u64)(unsigned)j;
                    c++;
                }
            }
            scnt[t] = c;
            atomicMax(&smax, c);
        }
        __syncthreads();
        if (t < 24){
            for (int k = scnt[t]; k < 16; k++) g_csr[t*16 + k] = 0ull;
        }
        if (t == 0) g_maxn = min(smax, 16);
    } else {
        const int r0 = (blk - 1) * 128;
        float* sw2   = dyn;
        float* chunk = dyn + 256;          // row stride 129
        float* sb1   = dyn + 256 + 128*129;

        if (t < 256) sw2[t] = fcw2[t];
        if (t < 128) sb1[t] = fcb1[t];
        const float* src = fcw1 + r0 * 128;
        for (int i = t; i < 16384; i += 768){
            int row = i >> 7, col = i & 127;
            chunk[row*129 + col] = src[i];
        }
        __syncthreads();

        if (t < 128){
            const float* row = chunk + t * 129;
            float a0 = 0.f, a1 = 0.f;
            #pragma unroll 8
            for (int k = 0; k < 128; k++){
                float w = row[k];
                a0 += w * sw2[2*k];
                a1 += w * sw2[2*k + 1];
            }
            int f = r0 + t;
            int node = f >> 5, fi = f & 31;
            g_wc[node*66 + 2*fi]     = a0;
            g_wc[node*66 + 2*fi + 1] = a1;
        }
        if (blk == 1 && t < 2){
            float b = fcb2[t];
            #pragma unroll 8
            for (int k = 0; k < 128; k++) b += sb1[k] * sw2[2*k + t];
            g_wc[1584 + t] = b;
        }
    }
}

// ---------- fused GCN kernel: warp = batch, lane = node, H in registers ----------
#define NT 256
#define TB 8

template<int FIN, int FOUT, int W2, int B2>
__device__ __forceinline__ void gcn_layer(float* h, const u64* csr, int maxn)
{
    float g[FIN];
    #pragma unroll
    for (int f = 0; f < FIN; f++) g[f] = 0.f;
    #pragma unroll 4
    for (int k = 0; k < maxn; k++){          // maxn block-uniform -> converged shfl
        u64 e = csr[k];
        int src = (int)(unsigned)e;
        float ak = __uint_as_float((unsigned)(e >> 32));
        #pragma unroll
        for (int f = 0; f < FIN; f++)
            g[f] = fmaf(ak, __shfl_sync(0xffffffffu, h[f], src), g[f]);
    }
    constexpr int KP = FOUT/2;
    u64 acc[KP];
    #pragma unroll
    for (int k = 0; k < KP; k++) acc[k] = c_WB2[CB_B + B2 + k];
    #pragma unroll
    for (int fi = 0; fi < FIN; fi++){
        u64 d = dup2(g[fi]);
        #pragma unroll
        for (int k = 0; k < KP; k++)
            acc[k] = fma2(d, c_WB2[W2 + fi*KP + k], acc[k]);
    }
    #pragma unroll
    for (int k = 0; k < KP; k++){
        float lo, hi; upk2(acc[k], lo, hi);
        h[2*k]   = fmaxf(lo, 0.f);
        h[2*k+1] = fmaxf(hi, 0.f);
    }
}

__global__ __launch_bounds__(NT, 4)
void gcn_fused_kernel(const float* __restrict__ x, float* __restrict__ out)
{
    __shared__ float sWc[1586];
    __shared__ u64   sCsr[24*17];     // stride 17: conflict-spread
    __shared__ int   sMx;

    const int t = threadIdx.x;
    const int warp = t >> 5;
    const int lane = t & 31;

    for (int i = t; i < 1586; i += NT) sWc[i] = g_wc[i];
    for (int i = t; i < 384;  i += NT) sCsr[(i >> 4)*17 + (i & 15)] = g_csr[i];
    if (t == 0) sMx = g_maxn;

    const int node = (lane < 24) ? lane : 0;
    const u64* csr = sCsr + node * 17;
    const int gb = blockIdx.x * TB + warp;

    float h[16];
    h[0] = (lane < 24) ? x[gb*24 + lane] : 0.f;
    __syncthreads();
    const int maxn = sMx;

    gcn_layer< 1,  4,   0,  0>(h, csr, maxn);
    gcn_layer< 4,  4,   2,  2>(h, csr, maxn);
    gcn_layer< 4,  8,  10,  4>(h, csr, maxn);
    gcn_layer< 8,  8,  26,  8>(h, csr, maxn);
    gcn_layer< 8, 16,  58, 12>(h, csr, maxn);
    gcn_layer<16, 16, 122, 20>(h, csr, maxn);

    // ---- layer 7 (16->32) + folded FC head: 4 passes of 8 outputs (acc[4]) ----
    float g[16];
    #pragma unroll
    for (int f = 0; f < 16; f++) g[f] = 0.f;
    #pragma unroll 4
    for (int k = 0; k < maxn; k++){
        u64 e = csr[k];
        int src = (int)(unsigned)e;
        float ak = __uint_as_float((unsigned)(e >> 32));
        #pragma unroll
        for (int f = 0; f < 16; f++)
            g[f] = fmaf(ak, __shfl_sync(0xffffffffu, h[f], src), g[f]);
    }
    u64 z = 0ull;
    const float* wcn = sWc + node * 66;
    #pragma unroll
    for (int pass = 0; pass < 4; pass++){
        u64 acc[4];
        #pragma unroll
        for (int k = 0; k < 4; k++) acc[k] = c_WB2[CB_B + 28 + pass*4 + k];
        #pragma unroll
        for (int fi = 0; fi < 16; fi++){
            u64 d = dup2(g[fi]);
            #pragma unroll
            for (int k = 0; k < 4; k++)
                acc[k] = fma2(d, c_WB2[250 + fi*16 + pass*4 + k], acc[k]);
        }
        const float* wcp = wcn + pass * 16;
        #pragma unroll
        for (int k = 0; k < 4; k++){
            float a, b; upk2(acc[k], a, b);
            z = fma2(dup2(fmaxf(a, 0.f)), lds2(wcp + 4*k),     z);
            z = fma2(dup2(fmaxf(b, 0.f)), lds2(wcp + 4*k + 2), z);
        }
    }
    if (lane >= 24) z = 0ull;

    #pragma unroll
    for (int m = 16; m >= 1; m >>= 1) z = add2(z, bfly64(z, m));
    if (lane == 0){
        z = add2(z, lds2(sWc + 1584));     // bc
        float z0, z1; upk2(z, z0, z1);
        float mx = fmaxf(z0, z1);
        float lse = mx + logf(expf(z0 - mx) + expf(z1 - mx));
        reinterpret_cast<u64*>(out)[gb] = pk2(z0 - lse, z1 - lse);
    }
}

extern "C" void kernel_launch(void* const* d_in, const int* in_sizes, int n_in,
                              void* d_out, int out_size)
{
    const float* x  = (const float*)d_in[0];
    const int*   ei = (const int*)d_in[1];
    float* out = (float*)d_out;

    const int B = in_sizes[0] / 24;
    const int grid = B / TB;           // 4096

    cudaFuncSetAttribute(prologue_kernel,
                         cudaFuncAttributeMaxDynamicSharedMemorySize, PRO_SMEM_BYTES);

    prologue_kernel<<<7, 768, PRO_SMEM_BYTES>>>(ei,
        (const float*)d_in[2],  (const float*)d_in[3],
        (const float*)d_in[4],  (const float*)d_in[5],
        (const float*)d_in[6],  (const float*)d_in[7],
        (const float*)d_in[8],  (const float*)d_in[9],
        (const float*)d_in[10], (const float*)d_in[11],
        (const float*)d_in[12], (const float*)d_in[13],
        (const float*)d_in[14], (const float*)d_in[15],
        (const float*)d_in[16], (const float*)d_in[17],
        (const float*)d_in[18], (const float*)d_in[19]);

    void* packAddr = nullptr;
    void* cAddr = nullptr;
    cudaGetSymbolAddress(&packAddr, g_pack);
    cudaGetSymbolAddress(&cAddr, c_WB2);
    cudaMemcpyAsync(cAddr, packAddr, 1100*4, cudaMemcpyDeviceToDevice, 0);

    gcn_fused_kernel<<<grid, NT>>>(x, out);
}

// round 16
// speedup vs baseline: 1.7421x; 1.1303x over previous
#include <cuda_runtime.h>
#include <math.h>

typedef unsigned long long u64;

__device__ __forceinline__ u64 dup2(float v){
    u64 r; asm("mov.b64 %0, {%1, %1};" : "=l"(r) : "f"(v)); return r;
}
__device__ __forceinline__ u64 pk2(float lo, float hi){
    u64 r; asm("mov.b64 %0, {%1, %2};" : "=l"(r) : "f"(lo), "f"(hi)); return r;
}
__device__ __forceinline__ void upk2(u64 a, float &lo, float &hi){
    asm("mov.b64 {%0, %1}, %2;" : "=f"(lo), "=f"(hi) : "l"(a));
}
__device__ __forceinline__ u64 fma2(u64 a, u64 b, u64 c){
    u64 d; asm("fma.rn.f32x2 %0, %1, %2, %3;" : "=l"(d) : "l"(a), "l"(b), "l"(c)); return d;
}
__device__ __forceinline__ u64 add2(u64 a, u64 b){
    u64 c; asm("add.rn.f32x2 %0, %1, %2;" : "=l"(c) : "l"(a), "l"(b)); return c;
}
__device__ __forceinline__ u64 lds2(const float* p){ return *reinterpret_cast<const u64*>(p); }
__device__ __forceinline__ u64 bfly64(u64 v, int m){
    unsigned lo = (unsigned)v, hi = (unsigned)(v >> 32);
    lo = __shfl_xor_sync(0xffffffffu, lo, m);
    hi = __shfl_xor_sync(0xffffffffu, hi, m);
    return ((u64)hi << 32) | (u64)lo;
}

// ---------- one fused constant bank: W (u64 0..505) then b (u64 506..549) ----------
__constant__ u64 c_WB2[550];
#define CB_B 506

// ---------- device globals ----------
__device__ float g_wc[1586];     // Wc padded: node stride 66, bc at [1584..1585]
__device__ float g_pack[1100];   // staging for c_WB2
__device__ u64   g_csr[512];     // 32 lanes x 16 entries: (f32 a)<<32 | src_node
__device__ u64   g_hlp[32];      // per lane: (f32 has)<<32 | helper_idx
__device__ int   g_maxn;

// ---------- parallel prologue: 7 blocks x 768 threads ----------
constexpr int PRO_SMEM_FLOATS = 256 + 128*129 + 128;
constexpr int PRO_SMEM_BYTES  = PRO_SMEM_FLOATS * 4;

__global__ void prologue_kernel(const int* __restrict__ ei_raw,
                                const float* __restrict__ W1, const float* __restrict__ b1,
                                const float* __restrict__ W2, const float* __restrict__ b2,
                                const float* __restrict__ W3, const float* __restrict__ b3,
                                const float* __restrict__ W4, const float* __restrict__ b4,
                                const float* __restrict__ W5, const float* __restrict__ b5,
                                const float* __restrict__ W6, const float* __restrict__ b6,
                                const float* __restrict__ W7, const float* __restrict__ b7,
                                const float* __restrict__ fcw1, const float* __restrict__ fcb1,
                                const float* __restrict__ fcw2, const float* __restrict__ fcb2){
    extern __shared__ float dyn[];
    int t = threadIdx.x;                     // 768 threads
    int blk = blockIdx.x;

    if (blk == 0){
        if (t < 4)    g_pack[0    + t] = W1[t];
        if (t < 16)   g_pack[4    + t] = W2[t];
        if (t < 32)   g_pack[20   + t] = W3[t];
        if (t < 64)   g_pack[52   + t] = W4[t];
        if (t < 128)  g_pack[116  + t] = W5[t];
        if (t < 256)  g_pack[244  + t] = W6[t];
        if (t < 512)  g_pack[500  + t] = W7[t];
        if (t < 4)    g_pack[1012 + t] = b1[t];
        if (t < 4)    g_pack[1016 + t] = b2[t];
        if (t < 8)    g_pack[1020 + t] = b3[t];
        if (t < 8)    g_pack[1028 + t] = b4[t];
        if (t < 16)   g_pack[1036 + t] = b5[t];
        if (t < 16)   g_pack[1052 + t] = b6[t];
        if (t < 32)   g_pack[1068 + t] = b7[t];

        __shared__ float sdeg[24], sdinv[24], sAl[576];
        __shared__ int ssrc[96], sdst[96];
        __shared__ u64 sEnt[24][24];          // per-row entry lists
        __shared__ int snnz[24], sKeep[24], sHlpOf[24], sHelped[24];
        __shared__ int sRowL[32], sBegL[32], sEndL[32];

        int myok = (t < 96) ? (ei_raw[2*t + 1] == 0) : 1;
        int is64 = __syncthreads_and(myok);

        if (t < 24) sdeg[t] = 1.0f;
        if (t < 576) sAl[t] = 0.0f;
        __syncthreads();
        if (t < 96){
            int s, d;
            if (is64){
                const long long* e = reinterpret_cast<const long long*>(ei_raw);
                s = (int)e[t]; d = (int)e[96 + t];
            } else { s = ei_raw[t]; d = ei_raw[96 + t]; }
            s = min(max(s,0),23); d = min(max(d,0),23);
            ssrc[t] = s; sdst[t] = d;
            atomicAdd(&sdeg[d], 1.0f);
        }
        __syncthreads();
        if (t < 24) sdinv[t] = 1.0f / sqrtf(sdeg[t]);
        __syncthreads();
        if (t < 96) atomicAdd(&sAl[sdst[t]*24 + ssrc[t]], sdinv[ssrc[t]]*sdinv[sdst[t]]);
        if (t < 24) atomicAdd(&sAl[t*24 + t], sdinv[t]*sdinv[t]);
        __syncthreads();

        // per-row entry lists
        if (t < 24){
            int c = 0;
            #pragma unroll 1
            for (int j = 0; j < 24; j++){
                float a = sAl[t*24 + j];
                if (a != 0.0f){
                    sEnt[t][c] = ((u64)__float_as_uint(a) << 32) | (u64)(unsigned)j;
                    c++;
                }
            }
            snnz[t] = c;
            sKeep[t] = c;
            sHlpOf[t] = t;      // self = no helper
            sHelped[t] = 0;
        }
        if (t >= 24 && t < 32){ sRowL[t] = 0; sBegL[t] = 0; sEndL[t] = 0; }
        __syncthreads();

        // greedy: split the 8 heaviest rows, tail half -> helper lane 24+s
        if (t == 0){
            for (int s = 0; s < 8; s++){
                int best = -1, bv = 1;       // only split rows with keep >= 2
                for (int r = 0; r < 24; r++)
                    if (!sHelped[r] && sKeep[r] > bv){ bv = sKeep[r]; best = r; }
                if (best < 0) break;
                int tot = sKeep[best], kp = (tot + 1) >> 1;
                sHelped[best] = 1;
                sHlpOf[best] = 24 + s;
                sRowL[24 + s] = best; sBegL[24 + s] = kp; sEndL[24 + s] = tot;
                sKeep[best] = kp;
            }
            int mx = 0;
            for (int r = 0; r < 24; r++) mx = max(mx, sKeep[r]);
            for (int l = 24; l < 32; l++) mx = max(mx, sEndL[l] - sBegL[l]);
            g_maxn = min(mx, 16);
        }
        __syncthreads();
        if (t < 24){ sRowL[t] = t; sBegL[t] = 0; sEndL[t] = sKeep[t]; }
        __syncthreads();

        // write padded per-lane CSR + helper map
        if (t < 32){
            int row = sRowL[t], b0 = sBegL[t], e0 = sEndL[t];
            int len = e0 - b0;
            for (int k = 0; k < 16; k++)
                g_csr[t*16 + k] = (k < len) ? sEnt[row][b0 + k] : 0ull;
            int idx; float has;
            if (t < 24){ idx = sHlpOf[t]; has = (idx != t) ? 1.0f : 0.0f; }
            else       { idx = t;         has = 0.0f; }
            g_hlp[t] = ((u64)__float_as_uint(has) << 32) | (u64)(unsigned)idx;
        }
    } else {
        const int r0 = (blk - 1) * 128;
        float* sw2   = dyn;
        float* chunk = dyn + 256;          // row stride 129
        float* sb1   = dyn + 256 + 128*129;

        if (t < 256) sw2[t] = fcw2[t];
        if (t < 128) sb1[t] = fcb1[t];
        const float* src = fcw1 + r0 * 128;
        for (int i = t; i < 16384; i += 768){
            int row = i >> 7, col = i & 127;
            chunk[row*129 + col] = src[i];
        }
        __syncthreads();

        if (t < 128){
            const float* row = chunk + t * 129;
            float a0 = 0.f, a1 = 0.f;
            #pragma unroll 8
            for (int k = 0; k < 128; k++){
                float w = row[k];
                a0 += w * sw2[2*k];
                a1 += w * sw2[2*k + 1];
            }
            int f = r0 + t;
            int node = f >> 5, fi = f & 31;
            g_wc[node*66 + 2*fi]     = a0;
            g_wc[node*66 + 2*fi + 1] = a1;
        }
        if (blk == 1 && t < 2){
            float b = fcb2[t];
            #pragma unroll 8
            for (int k = 0; k < 128; k++) b += sb1[k] * sw2[2*k + t];
            g_wc[1584 + t] = b;
        }
    }
}

// ---------- fused GCN kernel: warp = batch, lane = node (+8 helper lanes) ----------
#define NT 256
#define TB 8

template<int FIN, int FOUT, int W2, int B2>
__device__ __forceinline__ void gcn_layer(float* h, const u64* csr, int maxn,
                                          int hidx, float has)
{
    float g[FIN];
    #pragma unroll
    for (int f = 0; f < FIN; f++) g[f] = 0.f;
    #pragma unroll 4
    for (int k = 0; k < maxn; k++){          // maxn block-uniform -> converged shfl
        u64 e = csr[k];
        int src = (int)(unsigned)e;
        float ak = __uint_as_float((unsigned)(e >> 32));
        #pragma unroll
        for (int f = 0; f < FIN; f++)
            g[f] = fmaf(ak, __shfl_sync(0xffffffffu, h[f], src), g[f]);
    }
    // merge helper-lane partials into owner rows
    #pragma unroll
    for (int f = 0; f < FIN; f++)
        g[f] = fmaf(has, __shfl_sync(0xffffffffu, g[f], hidx), g[f]);

    constexpr int KP = FOUT/2;
    u64 acc[KP];
    #pragma unroll
    for (int k = 0; k < KP; k++) acc[k] = c_WB2[CB_B + B2 + k];
    #pragma unroll
    for (int fi = 0; fi < FIN; fi++){
        u64 d = dup2(g[fi]);
        #pragma unroll
        for (int k = 0; k < KP; k++)
            acc[k] = fma2(d, c_WB2[W2 + fi*KP + k], acc[k]);
    }
    #pragma unroll
    for (int k = 0; k < KP; k++){
        float lo, hi; upk2(acc[k], lo, hi);
        h[2*k]   = fmaxf(lo, 0.f);
        h[2*k+1] = fmaxf(hi, 0.f);
    }
}

__global__ __launch_bounds__(NT, 4)
void gcn_fused_kernel(const float* __restrict__ x, float* __restrict__ out)
{
    __shared__ float sWc[1586];
    __shared__ u64   sCsr[32*17];     // stride 17: conflict-spread
    __shared__ u64   sHlp[32];
    __shared__ int   sMx;

    const int t = threadIdx.x;
    const int warp = t >> 5;
    const int lane = t & 31;

    for (int i = t; i < 1586; i += NT) sWc[i] = g_wc[i];
    for (int i = t; i < 512;  i += NT) sCsr[(i >> 4)*17 + (i & 15)] = g_csr[i];
    if (t < 32) sHlp[t] = g_hlp[t];
    if (t == 0) sMx = g_maxn;

    const int node = (lane < 24) ? lane : 0;
    const u64* csr = sCsr + lane * 17;
    const int gb = blockIdx.x * TB + warp;

    float h[16];
    h[0] = (lane < 24) ? x[gb*24 + lane] : 0.f;
    __syncthreads();
    const int maxn = sMx;
    u64 he = sHlp[lane];
    const int hidx = (int)(unsigned)he;
    const float has = __uint_as_float((unsigned)(he >> 32));

    gcn_layer< 1,  4,   0,  0>(h, csr, maxn, hidx, has);
    gcn_layer< 4,  4,   2,  2>(h, csr, maxn, hidx, has);
    gcn_layer< 4,  8,  10,  4>(h, csr, maxn, hidx, has);
    gcn_layer< 8,  8,  26,  8>(h, csr, maxn, hidx, has);
    gcn_layer< 8, 16,  58, 12>(h, csr, maxn, hidx, has);
    gcn_layer<16, 16, 122, 20>(h, csr, maxn, hidx, has);

    // ---- layer 7 (16->32) + folded FC head: 4 passes of acc[4] ----
    float g[16];
    #pragma unroll
    for (int f = 0; f < 16; f++) g[f] = 0.f;
    #pragma unroll 4
    for (int k = 0; k < maxn; k++){
        u64 e = csr[k];
        int src = (int)(unsigned)e;
        float ak = __uint_as_float((unsigned)(e >> 32));
        #pragma unroll
        for (int f = 0; f < 16; f++)
            g[f] = fmaf(ak, __shfl_sync(0xffffffffu, h[f], src), g[f]);
    }
    #pragma unroll
    for (int f = 0; f < 16; f++)
        g[f] = fmaf(has, __shfl_sync(0xffffffffu, g[f], hidx), g[f]);

    u64 z = 0ull;
    const float* wcn = sWc + node * 66;
    #pragma unroll
    for (int pass = 0; pass < 4; pass++){
        u64 acc[4];
        #pragma unroll
        for (int k = 0; k < 4; k++) acc[k] = c_WB2[CB_B + 28 + pass*4 + k];
        #pragma unroll
        for (int fi = 0; fi < 16; fi++){
            u64 d = dup2(g[fi]);
            #pragma unroll
            for (int k = 0; k < 4; k++)
                acc[k] = fma2(d, c_WB2[250 + fi*16 + pass*4 + k], acc[k]);
        }
        const float* wcp = wcn + pass * 16;
        #pragma unroll
        for (int k = 0; k < 4; k++){
            float a, b; upk2(acc[k], a, b);
            z = fma2(dup2(fmaxf(a, 0.f)), lds2(wcp + 4*k),     z);
            z = fma2(dup2(fmaxf(b, 0.f)), lds2(wcp + 4*k + 2), z);
        }
    }
    if (lane >= 24) z = 0ull;

    #pragma unroll
    for (int m = 16; m >= 1; m >>= 1) z = add2(z, bfly64(z, m));
    if (lane == 0){
        z = add2(z, lds2(sWc + 1584));     // bc
        float z0, z1; upk2(z, z0, z1);
        float mx = fmaxf(z0, z1);
        float lse = mx + logf(expf(z0 - mx) + expf(z1 - mx));
        reinterpret_cast<u64*>(out)[gb] = pk2(z0 - lse, z1 - lse);
    }
}

extern "C" void kernel_launch(void* const* d_in, const int* in_sizes, int n_in,
                              void* d_out, int out_size)
{
    const float* x  = (const float*)d_in[0];
    const int*   ei = (const int*)d_in[1];
    float* out = (float*)d_out;

    const int B = in_sizes[0] / 24;
    const int grid = B / TB;           // 4096

    cudaFuncSetAttribute(prologue_kernel,
                         cudaFuncAttributeMaxDynamicSharedMemorySize, PRO_SMEM_BYTES);

    prologue_kernel<<<7, 768, PRO_SMEM_BYTES>>>(ei,
        (const float*)d_in[2],  (const float*)d_in[3],
        (const float*)d_in[4],  (const float*)d_in[5],
        (const float*)d_in[6],  (const float*)d_in[7],
        (const float*)d_in[8],  (const float*)d_in[9],
        (const float*)d_in[10], (const float*)d_in[11],
        (const float*)d_in[12], (const float*)d_in[13],
        (const float*)d_in[14], (const float*)d_in[15],
        (const float*)d_in[16], (const float*)d_in[17],
        (const float*)d_in[18], (const float*)d_in[19]);

    void* packAddr = nullptr;
    void* cAddr = nullptr;
    cudaGetSymbolAddress(&packAddr, g_pack);
    cudaGetSymbolAddress(&cAddr, c_WB2);
    cudaMemcpyAsync(cAddr, packAddr, 1100*4, cudaMemcpyDeviceToDevice, 0);

    gcn_fused_kernel<<<grid, NT>>>(x, out);
}

// round 17
// speedup vs baseline: 1.8141x; 1.0413x over previous
#include <cuda_runtime.h>
#include <math.h>

typedef unsigned long long u64;

__device__ __forceinline__ u64 dup2(float v){
    u64 r; asm("mov.b64 %0, {%1, %1};" : "=l"(r) : "f"(v)); return r;
}
__device__ __forceinline__ u64 pk2(float lo, float hi){
    u64 r; asm("mov.b64 %0, {%1, %2};" : "=l"(r) : "f"(lo), "f"(hi)); return r;
}
__device__ __forceinline__ void upk2(u64 a, float &lo, float &hi){
    asm("mov.b64 {%0, %1}, %2;" : "=f"(lo), "=f"(hi) : "l"(a));
}
__device__ __forceinline__ u64 fma2(u64 a, u64 b, u64 c){
    u64 d; asm("fma.rn.f32x2 %0, %1, %2, %3;" : "=l"(d) : "l"(a), "l"(b), "l"(c)); return d;
}
__device__ __forceinline__ u64 add2(u64 a, u64 b){
    u64 c; asm("add.rn.f32x2 %0, %1, %2;" : "=l"(c) : "l"(a), "l"(b)); return c;
}
__device__ __forceinline__ u64 lds2(const float* p){ return *reinterpret_cast<const u64*>(p); }
__device__ __forceinline__ u64 bfly64(u64 v, int m){
    unsigned lo = (unsigned)v, hi = (unsigned)(v >> 32);
    lo = __shfl_xor_sync(0xffffffffu, lo, m);
    hi = __shfl_xor_sync(0xffffffffu, hi, m);
    return ((u64)hi << 32) | (u64)lo;
}
__device__ __forceinline__ u64 shfl64(u64 v, int src){
    unsigned lo = (unsigned)v, hi = (unsigned)(v >> 32);
    lo = __shfl_sync(0xffffffffu, lo, src);
    hi = __shfl_sync(0xffffffffu, hi, src);
    return ((u64)hi << 32) | (u64)lo;
}

// ---------- one fused constant bank: W (u64 0..505) then b (u64 506..549) ----------
__constant__ u64 c_WB2[550];
#define CB_B 506

// ---------- device globals ----------
__device__ float g_wc[1586];     // Wc padded: node stride 66, bc at [1584..1585]
__device__ float g_pack[1100];   // staging for c_WB2
__device__ u64   g_csr[512];     // 32 lanes x 16 entries: (f32 a)<<32 | src_node
__device__ u64   g_hlp[32];      // per lane: (f32 has)<<32 | helper_idx
__device__ int   g_maxn;

// ---------- parallel prologue: 13 blocks x 768 threads ----------
// block 0: adjacency + balanced CSR + weight packing; blocks 1..12: Wc (64 rows each)
constexpr int PRO_SMEM_FLOATS = 256 + 64*129 + 128;
constexpr int PRO_SMEM_BYTES  = PRO_SMEM_FLOATS * 4;   // ~34.6KB

__global__ void prologue_kernel(const int* __restrict__ ei_raw,
                                const float* __restrict__ W1, const float* __restrict__ b1,
                                const float* __restrict__ W2, const float* __restrict__ b2,
                                const float* __restrict__ W3, const float* __restrict__ b3,
                                const float* __restrict__ W4, const float* __restrict__ b4,
                                const float* __restrict__ W5, const float* __restrict__ b5,
                                const float* __restrict__ W6, const float* __restrict__ b6,
                                const float* __restrict__ W7, const float* __restrict__ b7,
                                const float* __restrict__ fcw1, const float* __restrict__ fcb1,
                                const float* __restrict__ fcw2, const float* __restrict__ fcb2){
    extern __shared__ float dyn[];
    int t = threadIdx.x;                     // 768 threads
    int blk = blockIdx.x;

    if (blk == 0){
        if (t < 4)    g_pack[0    + t] = W1[t];
        if (t < 16)   g_pack[4    + t] = W2[t];
        if (t < 32)   g_pack[20   + t] = W3[t];
        if (t < 64)   g_pack[52   + t] = W4[t];
        if (t < 128)  g_pack[116  + t] = W5[t];
        if (t < 256)  g_pack[244  + t] = W6[t];
        if (t < 512)  g_pack[500  + t] = W7[t];
        if (t < 4)    g_pack[1012 + t] = b1[t];
        if (t < 4)    g_pack[1016 + t] = b2[t];
        if (t < 8)    g_pack[1020 + t] = b3[t];
        if (t < 8)    g_pack[1028 + t] = b4[t];
        if (t < 16)   g_pack[1036 + t] = b5[t];
        if (t < 16)   g_pack[1052 + t] = b6[t];
        if (t < 32)   g_pack[1068 + t] = b7[t];

        __shared__ float sdeg[24], sdinv[24], sAl[576];
        __shared__ int ssrc[96], sdst[96];
        __shared__ u64 sEnt[24][24];
        __shared__ int snnz[24], sKeep[24], sHlpOf[24], sHelped[24];
        __shared__ int sRowL[32], sBegL[32], sEndL[32];

        int myok = (t < 96) ? (ei_raw[2*t + 1] == 0) : 1;
        int is64 = __syncthreads_and(myok);

        if (t < 24) sdeg[t] = 1.0f;
        if (t < 576) sAl[t] = 0.0f;
        __syncthreads();
        if (t < 96){
            int s, d;
            if (is64){
                const long long* e = reinterpret_cast<const long long*>(ei_raw);
                s = (int)e[t]; d = (int)e[96 + t];
            } else { s = ei_raw[t]; d = ei_raw[96 + t]; }
            s = min(max(s,0),23); d = min(max(d,0),23);
            ssrc[t] = s; sdst[t] = d;
            atomicAdd(&sdeg[d], 1.0f);
        }
        __syncthreads();
        if (t < 24) sdinv[t] = 1.0f / sqrtf(sdeg[t]);
        __syncthreads();
        if (t < 96) atomicAdd(&sAl[sdst[t]*24 + ssrc[t]], sdinv[ssrc[t]]*sdinv[sdst[t]]);
        if (t < 24) atomicAdd(&sAl[t*24 + t], sdinv[t]*sdinv[t]);
        __syncthreads();

        if (t < 24){
            int c = 0;
            #pragma unroll 1
            for (int j = 0; j < 24; j++){
                float a = sAl[t*24 + j];
                if (a != 0.0f){
                    sEnt[t][c] = ((u64)__float_as_uint(a) << 32) | (u64)(unsigned)j;
                    c++;
                }
            }
            snnz[t] = c;
            sKeep[t] = c;
            sHlpOf[t] = t;
            sHelped[t] = 0;
        }
        if (t >= 24 && t < 32){ sRowL[t] = 0; sBegL[t] = 0; sEndL[t] = 0; }
        __syncthreads();

        if (t == 0){
            for (int s = 0; s < 8; s++){
                int best = -1, bv = 1;
                for (int r = 0; r < 24; r++)
                    if (!sHelped[r] && sKeep[r] > bv){ bv = sKeep[r]; best = r; }
                if (best < 0) break;
                int tot = sKeep[best], kp = (tot + 1) >> 1;
                sHelped[best] = 1;
                sHlpOf[best] = 24 + s;
                sRowL[24 + s] = best; sBegL[24 + s] = kp; sEndL[24 + s] = tot;
                sKeep[best] = kp;
            }
            int mx = 0;
            for (int r = 0; r < 24; r++) mx = max(mx, sKeep[r]);
            for (int l = 24; l < 32; l++) mx = max(mx, sEndL[l] - sBegL[l]);
            g_maxn = min(mx, 16);
        }
        __syncthreads();
        if (t < 24){ sRowL[t] = t; sBegL[t] = 0; sEndL[t] = sKeep[t]; }
        __syncthreads();

        if (t < 32){
            int row = sRowL[t], b0 = sBegL[t], e0 = sEndL[t];
            int len = e0 - b0;
            for (int k = 0; k < 16; k++)
                g_csr[t*16 + k] = (k < len) ? sEnt[row][b0 + k] : 0ull;
            int idx; float has;
            if (t < 24){ idx = sHlpOf[t]; has = (idx != t) ? 1.0f : 0.0f; }
            else       { idx = t;         has = 0.0f; }
            g_hlp[t] = ((u64)__float_as_uint(has) << 32) | (u64)(unsigned)idx;
        }
    } else {
        // ---- Wc rows [r0, r0+64) ----
        const int r0 = (blk - 1) * 64;
        float* sw2   = dyn;
        float* chunk = dyn + 256;          // row stride 129
        float* sb1   = dyn + 256 + 64*129;

        if (t < 256) sw2[t] = fcw2[t];
        if (t < 128) sb1[t] = fcb1[t];
        const float* src = fcw1 + r0 * 128;
        for (int i = t; i < 8192; i += 768){
            int row = i >> 7, col = i & 127;
            chunk[row*129 + col] = src[i];
        }
        __syncthreads();

        if (t < 64){
            const float* row = chunk + t * 129;
            float a0 = 0.f, a1 = 0.f;
            #pragma unroll 8
            for (int k = 0; k < 128; k++){
                float w = row[k];
                a0 += w * sw2[2*k];
                a1 += w * sw2[2*k + 1];
            }
            int f = r0 + t;
            int node = f >> 5, fi = f & 31;
            g_wc[node*66 + 2*fi]     = a0;
            g_wc[node*66 + 2*fi + 1] = a1;
        }
        if (blk == 1 && t < 2){
            float b = fcb2[t];
            #pragma unroll 8
            for (int k = 0; k < 128; k++) b += sb1[k] * sw2[2*k + t];
            g_wc[1584 + t] = b;
        }
    }
}

// ---------- fused GCN kernel: warp = batch, lane = node (+8 helper lanes) ----------
#define NT 256
#define TB 8

// packed layer: h2 = FIN/2 u64 pairs in, FOUT/2 pairs out (in place)
template<int FIN, int FOUT, int W2, int B2>
__device__ __forceinline__ void gcn_layer(u64* h2, const u64* csr, int maxn,
                                          int hidx, u64 has2)
{
    constexpr int GP = FIN/2;
    constexpr int KP = FOUT/2;
    u64 g2[GP];
    #pragma unroll
    for (int p = 0; p < GP; p++) g2[p] = 0ull;
    #pragma unroll 4
    for (int k = 0; k < maxn; k++){          // maxn block-uniform -> converged shfl
        u64 e = csr[k];
        int src = (int)(unsigned)e;
        u64 a2 = dup2(__uint_as_float((unsigned)(e >> 32)));
        #pragma unroll
        for (int p = 0; p < GP; p++)
            g2[p] = fma2(a2, shfl64(h2[p], src), g2[p]);
    }
    // merge helper partials into owner rows
    #pragma unroll
    for (int p = 0; p < GP; p++)
        g2[p] = fma2(has2, shfl64(g2[p], hidx), g2[p]);

    u64 acc[KP];
    #pragma unroll
    for (int k = 0; k < KP; k++) acc[k] = c_WB2[CB_B + B2 + k];
    #pragma unroll
    for (int p = 0; p < GP; p++){
        float glo, ghi; upk2(g2[p], glo, ghi);
        u64 d0 = dup2(glo), d1 = dup2(ghi);
        #pragma unroll
        for (int k = 0; k < KP; k++)
            acc[k] = fma2(d0, c_WB2[W2 + (2*p)*KP + k], acc[k]);
        #pragma unroll
        for (int k = 0; k < KP; k++)
            acc[k] = fma2(d1, c_WB2[W2 + (2*p+1)*KP + k], acc[k]);
    }
    #pragma unroll
    for (int k = 0; k < KP; k++){
        float lo, hi; upk2(acc[k], lo, hi);
        h2[k] = pk2(fmaxf(lo, 0.f), fmaxf(hi, 0.f));
    }
}

__global__ __launch_bounds__(NT, 4)
void gcn_fused_kernel(const float* __restrict__ x, float* __restrict__ out)
{
    __shared__ float sWc[1586];
    __shared__ u64   sCsr[32*17];     // stride 17: conflict-spread
    __shared__ u64   sHlp[32];
    __shared__ int   sMx;

    const int t = threadIdx.x;
    const int warp = t >> 5;
    const int lane = t & 31;

    for (int i = t; i < 1586; i += NT) sWc[i] = g_wc[i];
    for (int i = t; i < 512;  i += NT) sCsr[(i >> 4)*17 + (i & 15)] = g_csr[i];
    if (t < 32) sHlp[t] = g_hlp[t];
    if (t == 0) sMx = g_maxn;

    const int node = (lane < 24) ? lane : 0;
    const u64* csr = sCsr + lane * 17;
    const int gb = blockIdx.x * TB + warp;

    float h0 = (lane < 24) ? x[gb*24 + lane] : 0.f;
    __syncthreads();
    const int maxn = sMx;
    u64 he = sHlp[lane];
    const int hidx = (int)(unsigned)he;
    const float has = __uint_as_float((unsigned)(he >> 32));
    const u64 has2 = dup2(has);

    u64 h2[8];

    // ---- layer 1 (1 -> 4), scalar gather ----
    {
        float g0 = 0.f;
        #pragma unroll 4
        for (int k = 0; k < maxn; k++){
            u64 e = csr[k];
            int src = (int)(unsigned)e;
            float ak = __uint_as_float((unsigned)(e >> 32));
            g0 = fmaf(ak, __shfl_sync(0xffffffffu, h0, src), g0);
        }
        g0 = fmaf(has, __shfl_sync(0xffffffffu, g0, hidx), g0);
        u64 d = dup2(g0);
        u64 a0 = fma2(d, c_WB2[0], c_WB2[CB_B + 0]);
        u64 a1 = fma2(d, c_WB2[1], c_WB2[CB_B + 1]);
        float lo, hi;
        upk2(a0, lo, hi); h2[0] = pk2(fmaxf(lo,0.f), fmaxf(hi,0.f));
        upk2(a1, lo, hi); h2[1] = pk2(fmaxf(lo,0.f), fmaxf(hi,0.f));
    }

    gcn_layer< 4,  4,   2,  2>(h2, csr, maxn, hidx, has2);
    gcn_layer< 4,  8,  10,  4>(h2, csr, maxn, hidx, has2);
    gcn_layer< 8,  8,  26,  8>(h2, csr, maxn, hidx, has2);
    gcn_layer< 8, 16,  58, 12>(h2, csr, maxn, hidx, has2);
    gcn_layer<16, 16, 122, 20>(h2, csr, maxn, hidx, has2);

    // ---- layer 7 (16->32) + folded FC head ----
    u64 g2[8];
    #pragma unroll
    for (int p = 0; p < 8; p++) g2[p] = 0ull;
    #pragma unroll 4
    for (int k = 0; k < maxn; k++){
        u64 e = csr[k];
        int src = (int)(unsigned)e;
        u64 a2 = dup2(__uint_as_float((unsigned)(e >> 32)));
        #pragma unroll
        for (int p = 0; p < 8; p++)
            g2[p] = fma2(a2, shfl64(h2[p], src), g2[p]);
    }
    #pragma unroll
    for (int p = 0; p < 8; p++)
        g2[p] = fma2(has2, shfl64(g2[p], hidx), g2[p]);

    float gs[16];
    #pragma unroll
    for (int p = 0; p < 8; p++) upk2(g2[p], gs[2*p], gs[2*p+1]);

    u64 z = 0ull;
    const float* wcn = sWc + node * 66;
    #pragma unroll
    for (int pass = 0; pass < 4; pass++){
        u64 acc[4];
        #pragma unroll
        for (int k = 0; k < 4; k++) acc[k] = c_WB2[CB_B + 28 + pass*4 + k];
        #pragma unroll
        for (int fi = 0; fi < 16; fi++){
            u64 d = dup2(gs[fi]);
            #pragma unroll
            for (int k = 0; k < 4; k++)
                acc[k] = fma2(d, c_WB2[250 + fi*16 + pass*4 + k], acc[k]);
        }
        const float* wcp = wcn + pass * 16;
        #pragma unroll
        for (int k = 0; k < 4; k++){
            float a, b; upk2(acc[k], a, b);
            z = fma2(dup2(fmaxf(a, 0.f)), lds2(wcp + 4*k),     z);
            z = fma2(dup2(fmaxf(b, 0.f)), lds2(wcp + 4*k + 2), z);
        }
    }
    if (lane >= 24) z = 0ull;

    #pragma unroll
    for (int m = 16; m >= 1; m >>= 1) z = add2(z, bfly64(z, m));
    if (lane == 0){
        z = add2(z, lds2(sWc + 1584));     // bc
        float z0, z1; upk2(z, z0, z1);
        float mx = fmaxf(z0, z1);
        float lse = mx + logf(expf(z0 - mx) + expf(z1 - mx));
        reinterpret_cast<u64*>(out)[gb] = pk2(z0 - lse, z1 - lse);
    }
}

extern "C" void kernel_launch(void* const* d_in, const int* in_sizes, int n_in,
                              void* d_out, int out_size)
{
    const float* x  = (const float*)d_in[0];
    const int*   ei = (const int*)d_in[1];
    float* out = (float*)d_out;

    const int B = in_sizes[0] / 24;
    const int grid = B / TB;           // 4096

    cudaFuncSetAttribute(prologue_kernel,
                         cudaFuncAttributeMaxDynamicSharedMemorySize, PRO_SMEM_BYTES);

    prologue_kernel<<<13, 768, PRO_SMEM_BYTES>>>(ei,
        (const float*)d_in[2],  (const float*)d_in[3],
        (const float*)d_in[4],  (const float*)d_in[5],
        (const float*)d_in[6],  (const float*)d_in[7],
        (const float*)d_in[8],  (const float*)d_in[9],
        (const float*)d_in[10], (const float*)d_in[11],
        (const float*)d_in[12], (const float*)d_in[13],
        (const float*)d_in[14], (const float*)d_in[15],
        (const float*)d_in[16], (const float*)d_in[17],
        (const float*)d_in[18], (const float*)d_in[19]);

    void* packAddr = nullptr;
    void* cAddr = nullptr;
    cudaGetSymbolAddress(&packAddr, g_pack);
    cudaGetSymbolAddress(&cAddr, c_WB2);
    cudaMemcpyAsync(cAddr, packAddr, 1100*4, cudaMemcpyDeviceToDevice, 0);

    gcn_fused_kernel<<<grid, NT>>>(x, out);
}